// round 7
// baseline (speedup 1.0000x reference)
#include <cuda_runtime.h>
#include <cuda_bf16.h>

// inputs [B=16, C=4, H=1024, W=1024] fp32, targets [16,1024,1024] int32.
// Output: scalar float.
//
// probs = softmax over C. For c in 1..3:
//   S1_c = sum_{t==c} p_c ; S2_c = sum p_c^2 ; cnt_c = count
//   mean = S1/(cnt+EPS); var = (S2 - 2*mean*S1 + mean^2*cnt)/(cnt+EPS)
//   out = sum_{cnt>0} var / (C-1)
//
// Single fused kernel: grid-stride streaming pass + last-CTA final reduce.

#define NBLOCKS 2048
#define NTHREADS 256
#define NQ 9   // s1[3], s2[3], cnt[3]

__device__ float g_partials[NQ * NBLOCKS];
__device__ unsigned g_ticket = 0;

__device__ __forceinline__ float warp_reduce_f(float v) {
    #pragma unroll
    for (int o = 16; o > 0; o >>= 1)
        v += __shfl_down_sync(0xFFFFFFFFu, v, o);
    return v;
}

__device__ __forceinline__ double warp_reduce_d(double v) {
    #pragma unroll
    for (int o = 16; o > 0; o >>= 1)
        v += __shfl_down_sync(0xFFFFFFFFu, v, o);
    return v;
}

__global__ void __launch_bounds__(NTHREADS)
icl_fused(const float* __restrict__ x, const int* __restrict__ tg,
          float* __restrict__ out) {
    const unsigned HW = 1u << 20;           // 1024*1024
    const unsigned NVEC = 1u << 22;         // 16M pixels / 4
    const unsigned STRIDE = NBLOCKS * NTHREADS;  // 1<<19 -> exactly 8 iters

    float s11 = 0.f, s12 = 0.f, s13 = 0.f;
    float q1 = 0.f, q2 = 0.f, q3 = 0.f;
    float c1 = 0.f, c2 = 0.f, c3 = 0.f;

    unsigned v = blockIdx.x * NTHREADS + threadIdx.x;

    #pragma unroll 2
    for (; v < NVEC; v += STRIDE) {
        unsigned p = v << 2;                 // pixel index (multiple of 4)
        unsigned b = p >> 20;                // batch
        unsigned s = p & (HW - 1);           // spatial offset
        unsigned base = ((b << 2) << 20) + s;

        float4 ch0 = *reinterpret_cast<const float4*>(x + base);
        float4 ch1 = *reinterpret_cast<const float4*>(x + base + HW);
        float4 ch2 = *reinterpret_cast<const float4*>(x + base + 2u * HW);
        float4 ch3 = *reinterpret_cast<const float4*>(x + base + 3u * HW);
        int4  t4  = *reinterpret_cast<const int4*>(tg + p);

        #define PIX(X0, X1, X2, X3, T) do {                                 \
            float e0 = __expf(X0), e1 = __expf(X1),                         \
                  e2 = __expf(X2), e3 = __expf(X3);                         \
            float inv = __fdividef(1.0f, e0 + e1 + e2 + e3);                \
            float p1 = e1 * inv, p2 = e2 * inv, p3 = e3 * inv;              \
            bool b1 = ((T) == 1), b2 = ((T) == 2), b3 = ((T) == 3);         \
            float v1 = b1 ? p1 : 0.f;                                       \
            float v2 = b2 ? p2 : 0.f;                                       \
            float v3 = b3 ? p3 : 0.f;                                       \
            s11 += v1; s12 += v2; s13 += v3;                                \
            q1 += v1 * v1; q2 += v2 * v2; q3 += v3 * v3;                    \
            c1 += b1 ? 1.f : 0.f;                                           \
            c2 += b2 ? 1.f : 0.f;                                           \
            c3 += b3 ? 1.f : 0.f;                                           \
        } while (0)

        PIX(ch0.x, ch1.x, ch2.x, ch3.x, t4.x);
        PIX(ch0.y, ch1.y, ch2.y, ch3.y, t4.y);
        PIX(ch0.z, ch1.z, ch2.z, ch3.z, t4.z);
        PIX(ch0.w, ch1.w, ch2.w, ch3.w, t4.w);
        #undef PIX
    }

    // ---- per-block reduction ----
    float vals[NQ] = {s11, s12, s13, q1, q2, q3, c1, c2, c3};
    __shared__ float sm[NTHREADS / 32][NQ];
    int lane = threadIdx.x & 31;
    int w = threadIdx.x >> 5;
    #pragma unroll
    for (int q = 0; q < NQ; q++) {
        float r = warp_reduce_f(vals[q]);
        if (lane == 0) sm[w][q] = r;
    }
    __syncthreads();

    __shared__ unsigned s_islast;
    if (threadIdx.x == 0) {
        #pragma unroll
        for (int q = 0; q < NQ; q++) {
            float tot = 0.f;
            #pragma unroll
            for (int ww = 0; ww < NTHREADS / 32; ww++) tot += sm[ww][q];
            g_partials[q * NBLOCKS + blockIdx.x] = tot;
        }
        __threadfence();   // make partials visible before the ticket
        unsigned old = atomicAdd(&g_ticket, 1u);
        s_islast = (old == NBLOCKS - 1u) ? 1u : 0u;
    }
    __syncthreads();

    if (s_islast == 0u) return;

    // ---- last CTA: final reduce (fixed order -> deterministic) ----
    if (threadIdx.x == 0) g_ticket = 0;   // reset for next graph replay

    double acc[NQ];
    #pragma unroll
    for (int q = 0; q < NQ; q++) acc[q] = 0.0;

    // NBLOCKS/NTHREADS = 8 strided rows per thread, coalesced per q.
    #pragma unroll
    for (unsigned i = 0; i < NBLOCKS / NTHREADS; i++) {
        unsigned idx = i * NTHREADS + threadIdx.x;
        #pragma unroll
        for (int q = 0; q < NQ; q++)
            acc[q] += (double)g_partials[q * NBLOCKS + idx];
    }

    __shared__ double smd[NTHREADS / 32][NQ];
    #pragma unroll
    for (int q = 0; q < NQ; q++) {
        double r = warp_reduce_d(acc[q]);
        if (lane == 0) smd[w][q] = r;
    }
    __syncthreads();

    if (threadIdx.x == 0) {
        double tot[NQ];
        #pragma unroll
        for (int q = 0; q < NQ; q++) {
            double t = 0.0;
            #pragma unroll
            for (int ww = 0; ww < NTHREADS / 32; ww++) t += smd[ww][q];
            tot[q] = t;
        }
        const double EPS = 1e-6;
        double intra = 0.0;
        #pragma unroll
        for (int c = 0; c < 3; c++) {
            double S1 = tot[c];
            double S2 = tot[3 + c];
            double cnt = tot[6 + c];
            double mean = S1 / (cnt + EPS);
            double var = (S2 - 2.0 * mean * S1 + mean * mean * cnt) / (cnt + EPS);
            if (cnt > 0.0) intra += var;
        }
        out[0] = (float)(intra / 3.0);
    }
}

extern "C" void kernel_launch(void* const* d_in, const int* in_sizes, int n_in,
                              void* d_out, int out_size) {
    const float* inputs = (const float*)d_in[0];
    const int* targets = (const int*)d_in[1];
    float* out = (float*)d_out;

    icl_fused<<<NBLOCKS, NTHREADS>>>(inputs, targets, out);
}

// round 8
// speedup vs baseline: 1.0101x; 1.0101x over previous
#include <cuda_runtime.h>
#include <cuda_bf16.h>

// inputs [B=16, C=4, H=1024, W=1024] fp32, targets [16,1024,1024] int32.
// Output: scalar float.
//
// probs = softmax over C. For c in 1..3:
//   S1_c = sum_{t==c} p_c ; S2_c = sum p_c^2 ; cnt_c = count
//   mean = S1/(cnt+EPS); var = (S2 - 2*mean*S1 + mean^2*cnt)/(cnt+EPS)
//   out = sum_{cnt>0} var / (C-1)
//
// Single fused kernel: grid-stride streaming pass + last-CTA final reduce.

#define NBLOCKS 2048
#define NTHREADS 256
#define NQ 9   // s1[3], s2[3], cnt[3]

__device__ float g_partials[NQ * NBLOCKS];
__device__ unsigned g_ticket = 0;

__device__ __forceinline__ float warp_reduce_f(float v) {
    #pragma unroll
    for (int o = 16; o > 0; o >>= 1)
        v += __shfl_down_sync(0xFFFFFFFFu, v, o);
    return v;
}

__device__ __forceinline__ double warp_reduce_d(double v) {
    #pragma unroll
    for (int o = 16; o > 0; o >>= 1)
        v += __shfl_down_sync(0xFFFFFFFFu, v, o);
    return v;
}

__global__ void __launch_bounds__(NTHREADS)
icl_fused(const float* __restrict__ x, const int* __restrict__ tg,
          float* __restrict__ out) {
    const unsigned HW = 1u << 20;           // 1024*1024
    const unsigned NVEC = 1u << 22;         // 16M pixels / 4
    const unsigned STRIDE = NBLOCKS * NTHREADS;  // 1<<19 -> exactly 8 iters

    float s11 = 0.f, s12 = 0.f, s13 = 0.f;
    float q1 = 0.f, q2 = 0.f, q3 = 0.f;
    float c1 = 0.f, c2 = 0.f, c3 = 0.f;

    unsigned v = blockIdx.x * NTHREADS + threadIdx.x;

    #pragma unroll 2
    for (; v < NVEC; v += STRIDE) {
        unsigned p = v << 2;                 // pixel index (multiple of 4)
        unsigned b = p >> 20;                // batch
        unsigned s = p & (HW - 1);           // spatial offset
        unsigned base = ((b << 2) << 20) + s;

        float4 ch0 = *reinterpret_cast<const float4*>(x + base);
        float4 ch1 = *reinterpret_cast<const float4*>(x + base + HW);
        float4 ch2 = *reinterpret_cast<const float4*>(x + base + 2u * HW);
        float4 ch3 = *reinterpret_cast<const float4*>(x + base + 3u * HW);
        int4  t4  = *reinterpret_cast<const int4*>(tg + p);

        #define PIX(X0, X1, X2, X3, T) do {                                 \
            float e0 = __expf(X0), e1 = __expf(X1),                         \
                  e2 = __expf(X2), e3 = __expf(X3);                         \
            float inv = __fdividef(1.0f, e0 + e1 + e2 + e3);                \
            float p1 = e1 * inv, p2 = e2 * inv, p3 = e3 * inv;              \
            bool b1 = ((T) == 1), b2 = ((T) == 2), b3 = ((T) == 3);         \
            float v1 = b1 ? p1 : 0.f;                                       \
            float v2 = b2 ? p2 : 0.f;                                       \
            float v3 = b3 ? p3 : 0.f;                                       \
            s11 += v1; s12 += v2; s13 += v3;                                \
            q1 += v1 * v1; q2 += v2 * v2; q3 += v3 * v3;                    \
            c1 += b1 ? 1.f : 0.f;                                           \
            c2 += b2 ? 1.f : 0.f;                                           \
            c3 += b3 ? 1.f : 0.f;                                           \
        } while (0)

        PIX(ch0.x, ch1.x, ch2.x, ch3.x, t4.x);
        PIX(ch0.y, ch1.y, ch2.y, ch3.y, t4.y);
        PIX(ch0.z, ch1.z, ch2.z, ch3.z, t4.z);
        PIX(ch0.w, ch1.w, ch2.w, ch3.w, t4.w);
        #undef PIX
    }

    // ---- per-block reduction ----
    float vals[NQ] = {s11, s12, s13, q1, q2, q3, c1, c2, c3};
    __shared__ float sm[NTHREADS / 32][NQ];
    int lane = threadIdx.x & 31;
    int w = threadIdx.x >> 5;
    #pragma unroll
    for (int q = 0; q < NQ; q++) {
        float r = warp_reduce_f(vals[q]);
        if (lane == 0) sm[w][q] = r;
    }
    __syncthreads();

    __shared__ unsigned s_islast;
    if (threadIdx.x == 0) {
        #pragma unroll
        for (int q = 0; q < NQ; q++) {
            float tot = 0.f;
            #pragma unroll
            for (int ww = 0; ww < NTHREADS / 32; ww++) tot += sm[ww][q];
            g_partials[q * NBLOCKS + blockIdx.x] = tot;
        }
        __threadfence();   // make partials visible before the ticket
        unsigned old = atomicAdd(&g_ticket, 1u);
        s_islast = (old == NBLOCKS - 1u) ? 1u : 0u;
    }
    __syncthreads();

    if (s_islast == 0u) return;

    // ---- last CTA: final reduce (fixed order -> deterministic) ----
    if (threadIdx.x == 0) g_ticket = 0;   // reset for next graph replay

    double acc[NQ];
    #pragma unroll
    for (int q = 0; q < NQ; q++) acc[q] = 0.0;

    // NBLOCKS/NTHREADS = 8 strided rows per thread, coalesced per q.
    #pragma unroll
    for (unsigned i = 0; i < NBLOCKS / NTHREADS; i++) {
        unsigned idx = i * NTHREADS + threadIdx.x;
        #pragma unroll
        for (int q = 0; q < NQ; q++)
            acc[q] += (double)g_partials[q * NBLOCKS + idx];
    }

    __shared__ double smd[NTHREADS / 32][NQ];
    #pragma unroll
    for (int q = 0; q < NQ; q++) {
        double r = warp_reduce_d(acc[q]);
        if (lane == 0) smd[w][q] = r;
    }
    __syncthreads();

    if (threadIdx.x == 0) {
        double tot[NQ];
        #pragma unroll
        for (int q = 0; q < NQ; q++) {
            double t = 0.0;
            #pragma unroll
            for (int ww = 0; ww < NTHREADS / 32; ww++) t += smd[ww][q];
            tot[q] = t;
        }
        const double EPS = 1e-6;
        double intra = 0.0;
        #pragma unroll
        for (int c = 0; c < 3; c++) {
            double S1 = tot[c];
            double S2 = tot[3 + c];
            double cnt = tot[6 + c];
            double mean = S1 / (cnt + EPS);
            double var = (S2 - 2.0 * mean * S1 + mean * mean * cnt) / (cnt + EPS);
            if (cnt > 0.0) intra += var;
        }
        out[0] = (float)(intra / 3.0);
    }
}

extern "C" void kernel_launch(void* const* d_in, const int* in_sizes, int n_in,
                              void* d_out, int out_size) {
    const float* inputs = (const float*)d_in[0];
    const int* targets = (const int*)d_in[1];
    float* out = (float*)d_out;

    icl_fused<<<NBLOCKS, NTHREADS>>>(inputs, targets, out);
}

// round 9
// speedup vs baseline: 1.0126x; 1.0024x over previous
#include <cuda_runtime.h>
#include <cuda_bf16.h>

// inputs [B=16, C=4, H=1024, W=1024] fp32, targets [16,1024,1024] int32.
// Output: scalar float.
//
// probs = softmax over C. For c in 1..3:
//   S1_c = sum_{t==c} p_c ; S2_c = sum p_c^2 ; cnt_c = count
//   mean = S1/(cnt+EPS); var = (S2 - 2*mean*S1 + mean^2*cnt)/(cnt+EPS)
//   out = sum_{cnt>0} var / (C-1)
//
// Single fused kernel: grid-stride streaming pass + last-CTA final reduce.

#define NBLOCKS 2048
#define NTHREADS 256
#define NQ 9   // s1[3], s2[3], cnt[3]

__device__ float g_partials[NQ * NBLOCKS];
__device__ unsigned g_ticket = 0;

__device__ __forceinline__ float warp_reduce_f(float v) {
    #pragma unroll
    for (int o = 16; o > 0; o >>= 1)
        v += __shfl_down_sync(0xFFFFFFFFu, v, o);
    return v;
}

__device__ __forceinline__ double warp_reduce_d(double v) {
    #pragma unroll
    for (int o = 16; o > 0; o >>= 1)
        v += __shfl_down_sync(0xFFFFFFFFu, v, o);
    return v;
}

__global__ void __launch_bounds__(NTHREADS)
icl_fused(const float* __restrict__ x, const int* __restrict__ tg,
          float* __restrict__ out) {
    const unsigned HW = 1u << 20;           // 1024*1024
    const unsigned NVEC = 1u << 22;         // 16M pixels / 4
    const unsigned STRIDE = NBLOCKS * NTHREADS;  // 1<<19 -> exactly 8 iters

    float s11 = 0.f, s12 = 0.f, s13 = 0.f;
    float q1 = 0.f, q2 = 0.f, q3 = 0.f;
    float c1 = 0.f, c2 = 0.f, c3 = 0.f;

    unsigned v = blockIdx.x * NTHREADS + threadIdx.x;

    #pragma unroll 2
    for (; v < NVEC; v += STRIDE) {
        unsigned p = v << 2;                 // pixel index (multiple of 4)
        unsigned b = p >> 20;                // batch
        unsigned s = p & (HW - 1);           // spatial offset
        unsigned base = ((b << 2) << 20) + s;

        float4 ch0 = *reinterpret_cast<const float4*>(x + base);
        float4 ch1 = *reinterpret_cast<const float4*>(x + base + HW);
        float4 ch2 = *reinterpret_cast<const float4*>(x + base + 2u * HW);
        float4 ch3 = *reinterpret_cast<const float4*>(x + base + 3u * HW);
        int4  t4  = *reinterpret_cast<const int4*>(tg + p);

        #define PIX(X0, X1, X2, X3, T) do {                                 \
            float e0 = __expf(X0), e1 = __expf(X1),                         \
                  e2 = __expf(X2), e3 = __expf(X3);                         \
            float inv = __fdividef(1.0f, e0 + e1 + e2 + e3);                \
            float p1 = e1 * inv, p2 = e2 * inv, p3 = e3 * inv;              \
            bool b1 = ((T) == 1), b2 = ((T) == 2), b3 = ((T) == 3);         \
            float v1 = b1 ? p1 : 0.f;                                       \
            float v2 = b2 ? p2 : 0.f;                                       \
            float v3 = b3 ? p3 : 0.f;                                       \
            s11 += v1; s12 += v2; s13 += v3;                                \
            q1 += v1 * v1; q2 += v2 * v2; q3 += v3 * v3;                    \
            c1 += b1 ? 1.f : 0.f;                                           \
            c2 += b2 ? 1.f : 0.f;                                           \
            c3 += b3 ? 1.f : 0.f;                                           \
        } while (0)

        PIX(ch0.x, ch1.x, ch2.x, ch3.x, t4.x);
        PIX(ch0.y, ch1.y, ch2.y, ch3.y, t4.y);
        PIX(ch0.z, ch1.z, ch2.z, ch3.z, t4.z);
        PIX(ch0.w, ch1.w, ch2.w, ch3.w, t4.w);
        #undef PIX
    }

    // ---- per-block reduction ----
    float vals[NQ] = {s11, s12, s13, q1, q2, q3, c1, c2, c3};
    __shared__ float sm[NTHREADS / 32][NQ];
    int lane = threadIdx.x & 31;
    int w = threadIdx.x >> 5;
    #pragma unroll
    for (int q = 0; q < NQ; q++) {
        float r = warp_reduce_f(vals[q]);
        if (lane == 0) sm[w][q] = r;
    }
    __syncthreads();

    __shared__ unsigned s_islast;
    if (threadIdx.x == 0) {
        #pragma unroll
        for (int q = 0; q < NQ; q++) {
            float tot = 0.f;
            #pragma unroll
            for (int ww = 0; ww < NTHREADS / 32; ww++) tot += sm[ww][q];
            g_partials[q * NBLOCKS + blockIdx.x] = tot;
        }
        __threadfence();   // make partials visible before the ticket
        unsigned old = atomicAdd(&g_ticket, 1u);
        s_islast = (old == NBLOCKS - 1u) ? 1u : 0u;
    }
    __syncthreads();

    if (s_islast == 0u) return;

    // ---- last CTA: final reduce (fixed order -> deterministic) ----
    if (threadIdx.x == 0) g_ticket = 0;   // reset for next graph replay

    double acc[NQ];
    #pragma unroll
    for (int q = 0; q < NQ; q++) acc[q] = 0.0;

    // NBLOCKS/NTHREADS = 8 strided rows per thread, coalesced per q.
    #pragma unroll
    for (unsigned i = 0; i < NBLOCKS / NTHREADS; i++) {
        unsigned idx = i * NTHREADS + threadIdx.x;
        #pragma unroll
        for (int q = 0; q < NQ; q++)
            acc[q] += (double)g_partials[q * NBLOCKS + idx];
    }

    __shared__ double smd[NTHREADS / 32][NQ];
    #pragma unroll
    for (int q = 0; q < NQ; q++) {
        double r = warp_reduce_d(acc[q]);
        if (lane == 0) smd[w][q] = r;
    }
    __syncthreads();

    if (threadIdx.x == 0) {
        double tot[NQ];
        #pragma unroll
        for (int q = 0; q < NQ; q++) {
            double t = 0.0;
            #pragma unroll
            for (int ww = 0; ww < NTHREADS / 32; ww++) t += smd[ww][q];
            tot[q] = t;
        }
        const double EPS = 1e-6;
        double intra = 0.0;
        #pragma unroll
        for (int c = 0; c < 3; c++) {
            double S1 = tot[c];
            double S2 = tot[3 + c];
            double cnt = tot[6 + c];
            double mean = S1 / (cnt + EPS);
            double var = (S2 - 2.0 * mean * S1 + mean * mean * cnt) / (cnt + EPS);
            if (cnt > 0.0) intra += var;
        }
        out[0] = (float)(intra / 3.0);
    }
}

extern "C" void kernel_launch(void* const* d_in, const int* in_sizes, int n_in,
                              void* d_out, int out_size) {
    const float* inputs = (const float*)d_in[0];
    const int* targets = (const int*)d_in[1];
    float* out = (float*)d_out;

    icl_fused<<<NBLOCKS, NTHREADS>>>(inputs, targets, out);
}

// round 10
// speedup vs baseline: 1.0188x; 1.0061x over previous
#include <cuda_runtime.h>
#include <cuda_bf16.h>

// inputs [B=16, C=4, H=1024, W=1024] fp32, targets [16,1024,1024] int32.
// Output: scalar float.
//
// probs = softmax over C. For c in 1..3:
//   S1_c = sum_{t==c} p_c ; S2_c = sum p_c^2 ; cnt_c = count
//   mean = S1/(cnt+EPS); var = (S2 - 2*mean*S1 + mean^2*cnt)/(cnt+EPS)
//   out = sum_{cnt>0} var / (C-1)
//
// Single fused kernel: grid-stride streaming pass + last-CTA final reduce.

#define NBLOCKS 2048
#define NTHREADS 256
#define NQ 9   // s1[3], s2[3], cnt[3]

__device__ float g_partials[NQ * NBLOCKS];
__device__ unsigned g_ticket = 0;

__device__ __forceinline__ float warp_reduce_f(float v) {
    #pragma unroll
    for (int o = 16; o > 0; o >>= 1)
        v += __shfl_down_sync(0xFFFFFFFFu, v, o);
    return v;
}

__device__ __forceinline__ double warp_reduce_d(double v) {
    #pragma unroll
    for (int o = 16; o > 0; o >>= 1)
        v += __shfl_down_sync(0xFFFFFFFFu, v, o);
    return v;
}

__global__ void __launch_bounds__(NTHREADS)
icl_fused(const float* __restrict__ x, const int* __restrict__ tg,
          float* __restrict__ out) {
    const unsigned HW = 1u << 20;           // 1024*1024
    const unsigned NVEC = 1u << 22;         // 16M pixels / 4
    const unsigned STRIDE = NBLOCKS * NTHREADS;  // 1<<19 -> exactly 8 iters

    float s11 = 0.f, s12 = 0.f, s13 = 0.f;
    float q1 = 0.f, q2 = 0.f, q3 = 0.f;
    float c1 = 0.f, c2 = 0.f, c3 = 0.f;

    unsigned v = blockIdx.x * NTHREADS + threadIdx.x;

    #pragma unroll 2
    for (; v < NVEC; v += STRIDE) {
        unsigned p = v << 2;                 // pixel index (multiple of 4)
        unsigned b = p >> 20;                // batch
        unsigned s = p & (HW - 1);           // spatial offset
        unsigned base = ((b << 2) << 20) + s;

        float4 ch0 = *reinterpret_cast<const float4*>(x + base);
        float4 ch1 = *reinterpret_cast<const float4*>(x + base + HW);
        float4 ch2 = *reinterpret_cast<const float4*>(x + base + 2u * HW);
        float4 ch3 = *reinterpret_cast<const float4*>(x + base + 3u * HW);
        int4  t4  = *reinterpret_cast<const int4*>(tg + p);

        #define PIX(X0, X1, X2, X3, T) do {                                 \
            float e0 = __expf(X0), e1 = __expf(X1),                         \
                  e2 = __expf(X2), e3 = __expf(X3);                         \
            float inv = __fdividef(1.0f, e0 + e1 + e2 + e3);                \
            float p1 = e1 * inv, p2 = e2 * inv, p3 = e3 * inv;              \
            bool b1 = ((T) == 1), b2 = ((T) == 2), b3 = ((T) == 3);         \
            float v1 = b1 ? p1 : 0.f;                                       \
            float v2 = b2 ? p2 : 0.f;                                       \
            float v3 = b3 ? p3 : 0.f;                                       \
            s11 += v1; s12 += v2; s13 += v3;                                \
            q1 += v1 * v1; q2 += v2 * v2; q3 += v3 * v3;                    \
            c1 += b1 ? 1.f : 0.f;                                           \
            c2 += b2 ? 1.f : 0.f;                                           \
            c3 += b3 ? 1.f : 0.f;                                           \
        } while (0)

        PIX(ch0.x, ch1.x, ch2.x, ch3.x, t4.x);
        PIX(ch0.y, ch1.y, ch2.y, ch3.y, t4.y);
        PIX(ch0.z, ch1.z, ch2.z, ch3.z, t4.z);
        PIX(ch0.w, ch1.w, ch2.w, ch3.w, t4.w);
        #undef PIX
    }

    // ---- per-block reduction ----
    float vals[NQ] = {s11, s12, s13, q1, q2, q3, c1, c2, c3};
    __shared__ float sm[NTHREADS / 32][NQ];
    int lane = threadIdx.x & 31;
    int w = threadIdx.x >> 5;
    #pragma unroll
    for (int q = 0; q < NQ; q++) {
        float r = warp_reduce_f(vals[q]);
        if (lane == 0) sm[w][q] = r;
    }
    __syncthreads();

    __shared__ unsigned s_islast;
    if (threadIdx.x == 0) {
        #pragma unroll
        for (int q = 0; q < NQ; q++) {
            float tot = 0.f;
            #pragma unroll
            for (int ww = 0; ww < NTHREADS / 32; ww++) tot += sm[ww][q];
            g_partials[q * NBLOCKS + blockIdx.x] = tot;
        }
        __threadfence();   // make partials visible before the ticket
        unsigned old = atomicAdd(&g_ticket, 1u);
        s_islast = (old == NBLOCKS - 1u) ? 1u : 0u;
    }
    __syncthreads();

    if (s_islast == 0u) return;

    // ---- last CTA: final reduce (fixed order -> deterministic) ----
    if (threadIdx.x == 0) g_ticket = 0;   // reset for next graph replay

    double acc[NQ];
    #pragma unroll
    for (int q = 0; q < NQ; q++) acc[q] = 0.0;

    // NBLOCKS/NTHREADS = 8 strided rows per thread, coalesced per q.
    #pragma unroll
    for (unsigned i = 0; i < NBLOCKS / NTHREADS; i++) {
        unsigned idx = i * NTHREADS + threadIdx.x;
        #pragma unroll
        for (int q = 0; q < NQ; q++)
            acc[q] += (double)g_partials[q * NBLOCKS + idx];
    }

    __shared__ double smd[NTHREADS / 32][NQ];
    #pragma unroll
    for (int q = 0; q < NQ; q++) {
        double r = warp_reduce_d(acc[q]);
        if (lane == 0) smd[w][q] = r;
    }
    __syncthreads();

    if (threadIdx.x == 0) {
        double tot[NQ];
        #pragma unroll
        for (int q = 0; q < NQ; q++) {
            double t = 0.0;
            #pragma unroll
            for (int ww = 0; ww < NTHREADS / 32; ww++) t += smd[ww][q];
            tot[q] = t;
        }
        const double EPS = 1e-6;
        double intra = 0.0;
        #pragma unroll
        for (int c = 0; c < 3; c++) {
            double S1 = tot[c];
            double S2 = tot[3 + c];
            double cnt = tot[6 + c];
            double mean = S1 / (cnt + EPS);
            double var = (S2 - 2.0 * mean * S1 + mean * mean * cnt) / (cnt + EPS);
            if (cnt > 0.0) intra += var;
        }
        out[0] = (float)(intra / 3.0);
    }
}

extern "C" void kernel_launch(void* const* d_in, const int* in_sizes, int n_in,
                              void* d_out, int out_size) {
    const float* inputs = (const float*)d_in[0];
    const int* targets = (const int*)d_in[1];
    float* out = (float*)d_out;

    icl_fused<<<NBLOCKS, NTHREADS>>>(inputs, targets, out);
}